// round 17
// baseline (speedup 1.0000x reference)
#include <cuda_runtime.h>
#include <cstdint>

// NNUE HalfKP forward — single launch, producer/consumer blocks (v2).
//   Producers (blocks 0..1279): R10 phaseA verbatim — (64 kings x 20 slices of
//     32 rows), 16 KB tile, 8 warps x 4 pairs, dense predicated-vadd2 -> g_part;
//     then threadfence + per-sample counter bumps (lane 0 only).
//     Block 0 pre-packs FC weights and sets a sticky ready flag.
//   Consumers (blocks 1280..1407, scheduled last): warp = sample; lane 0 polls
//     the sample counter with VOLATILE L2 LOADS (no atomics -> no L2-ALU storm),
//     then combines 40 partials (__ldcg, batches of 5) + king bias rows +
//     input_bias (mod 2^16 == astype(int16)), clip, FC1/FC2, output dot,
//     atomicAdd; unique last sample writes floor_div(total+out_b,16) as float
//     and self-resets scalars. Counters self-reset per sample. Replay-safe.
//
// Inputs (ALL integers widened to int32 by the harness):
//  0 piece_positions (B,640)  1 king_positions (B,2)  2 input_weights (64,641,256)
//  3 input_bias (256)  4 w1 (32,512)  5 b1 (32)  6 w2 (32,32)  7 b2 (32)
//  8 out_w (32)  9 out_b (1)        out: float32 (1)

#define NQ      20
#define QR      32
#define NPROD   (64 * NQ)        // 1280 producer blocks
#define MAXP    2048
#define MAXS    1024
#define BCAP    128
#define TARGET  (2 * NQ)         // 40 partial stores per sample

__device__ uint4    g_part[NQ][MAXP * 32];   // packed-int16 partials (20 MB)
__device__ unsigned g_w1t[128 * 32];
__device__ int      g_w2t[32 * 32];
__device__ int      g_scnt[MAXS];            // per-sample counters (self-reset)
__device__ int      g_total;                 // self-reset
__device__ int      g_done;                  // self-reset
__device__ int      g_wready;                // sticky

__global__ void __launch_bounds__(256, 4) hx_all(
    const int* __restrict__ W32,
    const int* __restrict__ pp,
    const int* __restrict__ kings,
    const int* __restrict__ w1,
    const int* __restrict__ w2,
    const int* __restrict__ bias,
    const int* __restrict__ b1,
    const int* __restrict__ b2,
    const int* __restrict__ ow,
    const int* __restrict__ ob,
    float* __restrict__ out,
    int B)
{
    __shared__ short    s_tile[QR * 256];   // 16 KB (producers)
    __shared__ int      s_bucket[BCAP];
    __shared__ int      s_cnt;
    __shared__ unsigned s_x[8][64];         // (consumers)
    __shared__ int      s_x1[8][32];

    const int warp = threadIdx.x >> 5;
    const int lane = threadIdx.x & 31;

    if (blockIdx.x < NPROD) {
        // ================= PRODUCER (R10 phaseA) =================
        const int k = blockIdx.x & 63;
        const int q = blockIdx.x >> 6;

        if (blockIdx.x == 0) {
            for (int t = threadIdx.x; t < 32 * 128; t += 256) {
                const int o = t >> 7, j = t & 127;
                const int* p = w1 + t * 4;
                g_w1t[j * 32 + o] =
                    (unsigned)(p[0] & 0xff) | ((unsigned)(p[1] & 0xff) << 8) |
                    ((unsigned)(p[2] & 0xff) << 16) | ((unsigned)p[3] << 24);
            }
            for (int t = threadIdx.x; t < 32 * 32; t += 256)
                g_w2t[(t & 31) * 32 + (t >> 5)] = w2[t];
            __syncthreads();
            __threadfence();
            if (threadIdx.x == 0) *((volatile int*)&g_wready) = 1;
        }
        if (threadIdx.x == 0) s_cnt = 0;

        const int P = 2 * B;
        int kv[8];
        int nk = 0;
        #pragma unroll
        for (int j = 0; j < 8; j++) {
            const int i = threadIdx.x + j * 256;
            if (i < P) { kv[nk] = kings[i]; nk++; }
        }

        {
            const int4* src = (const int4*)(W32 + ((size_t)k * 641 + (size_t)q * QR) * 256);
            short4* dst = (short4*)s_tile;
            #pragma unroll
            for (int i = threadIdx.x; i < QR * 256 / 4; i += 256) {
                const int4 v = src[i];
                dst[i] = make_short4((short)v.x, (short)v.y, (short)v.z, (short)v.w);
            }
        }

        __syncthreads();
        for (int j = 0; j < nk; j++)
            if (kv[j] == k) {
                const int slot = atomicAdd(&s_cnt, 1);
                if (slot < BCAP) s_bucket[slot] = threadIdx.x + j * 256;
            }
        __syncthreads();

        const int cnt = min(s_cnt, BCAP);
        const char* tb = (const char*)s_tile + lane * 16;

        for (int gb = warp * 4; gb < cnt; gb += 32) {
            const int npair = min(4, cnt - gb);

            unsigned m[4];
            int pid[4];
            #pragma unroll
            for (int j = 0; j < 4; j++) {
                const bool valid = (j < npair);
                const int  p = s_bucket[valid ? (gb + j) : gb];
                pid[j] = p;
                const int* ppq = pp + (size_t)(p >> 1) * 640 + q * QR;
                const unsigned b = __ballot_sync(0xffffffffu, ppq[lane] != 0);
                m[j] = valid ? b : 0u;
            }

            unsigned acc[4][4];
            #pragma unroll
            for (int j = 0; j < 4; j++)
                acc[j][0] = acc[j][1] = acc[j][2] = acc[j][3] = 0u;

            #pragma unroll
            for (int r = 0; r < QR; r++) {
                const uint4 row = *(const uint4*)(tb + (r << 9));
                #pragma unroll
                for (int j = 0; j < 4; j++) {
                    if (m[j] & (1u << r)) {
                        acc[j][0] = __vadd2(acc[j][0], row.x);
                        acc[j][1] = __vadd2(acc[j][1], row.y);
                        acc[j][2] = __vadd2(acc[j][2], row.z);
                        acc[j][3] = __vadd2(acc[j][3], row.w);
                    }
                }
            }

            #pragma unroll
            for (int j = 0; j < 4; j++)
                if (j < npair)
                    g_part[q][pid[j] * 32 + lane] =
                        make_uint4(acc[j][0], acc[j][1], acc[j][2], acc[j][3]);

            __threadfence();                 // release stores before counts
            if (lane == 0) {
                #pragma unroll
                for (int j = 0; j < 4; j++)
                    if (j < npair) atomicAdd(&g_scnt[pid[j] >> 1], 1);
            }
        }
    } else {
        // ================= CONSUMER =================
        const int s = (blockIdx.x - NPROD) * 8 + warp;
        if (s >= B) return;

        // poll with plain volatile L2 loads — no atomic-ALU traffic
        if (lane == 0) {
            const volatile int* c = (const volatile int*)&g_scnt[s];
            while (*c < TARGET) __nanosleep(400);
            const volatile int* wr = (const volatile int*)&g_wready;
            while (*wr == 0) __nanosleep(200);
            g_scnt[s] = 0;                   // self-reset (sole consumer of s)
        }
        __syncwarp();
        __threadfence();                     // acquire

        // combine 20 slices x 2 sides via __ldcg, batches of 5 (low reg peak)
        unsigned a0 = 0, a1 = 0, a2 = 0, a3 = 0;
        #pragma unroll
        for (int side = 0; side < 2; side++) {
            const int row = (2 * s + side) * 32 + lane;
            #pragma unroll
            for (int h = 0; h < 4; h++) {
                uint4 r[5];
                #pragma unroll
                for (int i = 0; i < 5; i++)
                    r[i] = __ldcg(&g_part[h * 5 + i][row]);
                #pragma unroll
                for (int i = 0; i < 5; i++) {
                    a0 = __vadd2(a0, r[i].x); a1 = __vadd2(a1, r[i].y);
                    a2 = __vadd2(a2, r[i].z); a3 = __vadd2(a3, r[i].w);
                }
            }
        }
        // king bias rows + input_bias
        const int k0 = kings[2 * s + 0];
        const int k1 = kings[2 * s + 1];
        const int4* br0 = (const int4*)(W32 + ((size_t)k0 * 641 + 640) * 256 + lane * 8);
        const int4* br1 = (const int4*)(W32 + ((size_t)k1 * 641 + 640) * 256 + lane * 8);
        const int4 u0 = br0[0], v0 = br0[1];
        const int4 u1 = br1[0], v1 = br1[1];
        const int4 bA = ((const int4*)bias)[lane * 2 + 0];
        const int4 bB = ((const int4*)bias)[lane * 2 + 1];
        a0 = __vadd2(a0, (unsigned)(u0.x & 0xffff) | ((unsigned)u0.y << 16));
        a1 = __vadd2(a1, (unsigned)(u0.z & 0xffff) | ((unsigned)u0.w << 16));
        a2 = __vadd2(a2, (unsigned)(v0.x & 0xffff) | ((unsigned)v0.y << 16));
        a3 = __vadd2(a3, (unsigned)(v0.z & 0xffff) | ((unsigned)v0.w << 16));
        a0 = __vadd2(a0, (unsigned)(u1.x & 0xffff) | ((unsigned)u1.y << 16));
        a1 = __vadd2(a1, (unsigned)(u1.z & 0xffff) | ((unsigned)u1.w << 16));
        a2 = __vadd2(a2, (unsigned)(v1.x & 0xffff) | ((unsigned)v1.y << 16));
        a3 = __vadd2(a3, (unsigned)(v1.z & 0xffff) | ((unsigned)v1.w << 16));
        a0 = __vadd2(a0, (unsigned)(bA.x & 0xffff) | ((unsigned)bA.y << 16));
        a1 = __vadd2(a1, (unsigned)(bA.z & 0xffff) | ((unsigned)bA.w << 16));
        a2 = __vadd2(a2, (unsigned)(bB.x & 0xffff) | ((unsigned)bB.y << 16));
        a3 = __vadd2(a3, (unsigned)(bB.z & 0xffff) | ((unsigned)bB.w << 16));

        // clip int16 -> [0,127], pack 8 int8 into 2 words
        unsigned accs[4] = {a0, a1, a2, a3};
        int c8[8];
        #pragma unroll
        for (int kk = 0; kk < 4; kk++) {
            int lo = (int)(short)(accs[kk] & 0xffffu);
            int hi = (int)(short)(accs[kk] >> 16);
            c8[2 * kk + 0] = min(max(lo, 0), 127);
            c8[2 * kk + 1] = min(max(hi, 0), 127);
        }
        s_x[warp][lane * 2 + 0] = (unsigned)c8[0] | ((unsigned)c8[1] << 8) |
                                  ((unsigned)c8[2] << 16) | ((unsigned)c8[3] << 24);
        s_x[warp][lane * 2 + 1] = (unsigned)c8[4] | ((unsigned)c8[5] << 8) |
                                  ((unsigned)c8[6] << 16) | ((unsigned)c8[7] << 24);
        __syncwarp();

        // FC1: lane = output unit; x512 = [x, x]; 4 independent dp4a chains
        int v1a = b1[lane], v1b = 0, v1c = 0, v1d = 0;
        #pragma unroll 8
        for (int j = 0; j < 64; j += 2) {
            const int x0 = (int)s_x[warp][j];
            const int x1 = (int)s_x[warp][j + 1];
            v1a = __dp4a(x0, (int)__ldg(&g_w1t[j * 32 + lane]),        v1a);
            v1b = __dp4a(x0, (int)__ldg(&g_w1t[(64 + j) * 32 + lane]), v1b);
            v1c = __dp4a(x1, (int)__ldg(&g_w1t[(j + 1) * 32 + lane]),  v1c);
            v1d = __dp4a(x1, (int)__ldg(&g_w1t[(65 + j) * 32 + lane]), v1d);
        }
        int v1s = (v1a + v1b) + (v1c + v1d);
        v1s >>= 6;
        v1s = min(max(v1s, 0), 127);
        s_x1[warp][lane] = v1s;
        __syncwarp();

        // FC2
        int v2a = b2[lane], v2b = 0;
        #pragma unroll 8
        for (int o = 0; o < 32; o += 2) {
            v2a += s_x1[warp][o]     * __ldg(&g_w2t[o * 32 + lane]);
            v2b += s_x1[warp][o + 1] * __ldg(&g_w2t[(o + 1) * 32 + lane]);
        }
        int v2 = v2a + v2b;
        v2 >>= 6;
        v2 = min(max(v2, 0), 127);

        int contrib = v2 * ow[lane];
        #pragma unroll
        for (int sh = 16; sh; sh >>= 1)
            contrib += __shfl_xor_sync(0xffffffffu, contrib, sh);

        if (lane == 0) {
            atomicAdd(&g_total, contrib);
            __threadfence();
            if (atomicAdd(&g_done, 1) == B - 1) {      // unique last sample
                const int tot = atomicAdd(&g_total, 0);
                out[0] = (float)((tot + ob[0]) >> 4);
                atomicExch(&g_total, 0);               // self-reset
                atomicExch(&g_done, 0);
            }
        }
    }
}

extern "C" void kernel_launch(void* const* d_in, const int* in_sizes, int n_in,
                              void* d_out, int out_size) {
    const int B = in_sizes[0] / 640;
    const int cblocks = (B + 7) / 8;
    hx_all<<<NPROD + cblocks, 256>>>(
        (const int*)d_in[2],
        (const int*)d_in[0],
        (const int*)d_in[1],
        (const int*)d_in[4],
        (const int*)d_in[6],
        (const int*)d_in[3],
        (const int*)d_in[5],
        (const int*)d_in[7],
        (const int*)d_in[8],
        (const int*)d_in[9],
        (float*)d_out,
        B);
}